// round 15
// baseline (speedup 1.0000x reference)
#include <cuda_runtime.h>
#include <cuda_bf16.h>
#include <cstdint>

#define MT 32768
#define TC 1024
#define TH 512
#define TO 1024
#define TR 32
#define FCAP (1 << 22)
#define TAU 6e-4f

__device__ float g_wres[(size_t)TO * TC];
__device__ __nv_bfloat16 g_qwb[(size_t)TO * TC];
__device__ float g_x[(size_t)MT * TC];               // rotated activations
__device__ __nv_bfloat16 g_qx[(size_t)MT * TC];      // activation codes
__device__ __nv_bfloat16 g_xh[(size_t)MT * TC];      // x split hi (bf16)
__device__ __nv_bfloat16 g_xm[(size_t)MT * TC];      // x split residual (bf16)
__device__ __nv_bfloat16 g_rh[2 * TH * TH];          // R^T split hi   [half][n][k]
__device__ __nv_bfloat16 g_rm[2 * TH * TH];          // R^T split res
__device__ float g_s0[MT];
__device__ float g_s1[MT];
__device__ float g_p[(size_t)MT * TR];
__device__ int g_flagcnt;
__device__ int g_flags[FCAP];
__device__ int g_aidx[MT * 2];

__device__ __forceinline__ float qcode(float v, float s) {
    float q = rintf(__fdiv_rn(v, s));
    return fminf(fmaxf(q, -8.0f), 7.0f);
}

// ---- shared MMA helpers (bf16 m16n8k16, ldmatrix, [row][k] smem, stride SMA) ----
#define SMA 40

__device__ __forceinline__ void mma_bf16(float* c, uint32_t a0, uint32_t a1,
                                         uint32_t a2, uint32_t a3,
                                         uint32_t b0, uint32_t b1) {
    asm volatile(
        "mma.sync.aligned.m16n8k16.row.col.f32.bf16.bf16.f32 "
        "{%0,%1,%2,%3}, {%4,%5,%6,%7}, {%8,%9}, {%0,%1,%2,%3};"
        : "+f"(c[0]), "+f"(c[1]), "+f"(c[2]), "+f"(c[3])
        : "r"(a0), "r"(a1), "r"(a2), "r"(a3), "r"(b0), "r"(b1));
}

__device__ __forceinline__ void ldsm4(uint32_t* r, uint32_t addr) {
    asm volatile("ldmatrix.sync.aligned.m8n8.x4.shared.b16 {%0,%1,%2,%3}, [%4];"
                 : "=r"(r[0]), "=r"(r[1]), "=r"(r[2]), "=r"(r[3]) : "r"(addr));
}

__device__ __forceinline__ void mm_compute(uint32_t aBase, uint32_t bBase,
                                           float (&acc)[4][4][4]) {
#pragma unroll
    for (int ks = 0; ks < 2; ks++) {
        uint32_t a[4][4], b[2][4];
#pragma unroll
        for (int mi = 0; mi < 4; mi++) ldsm4(a[mi], aBase + mi * (16 * SMA * 2) + ks * 32);
#pragma unroll
        for (int p = 0; p < 2; p++) ldsm4(b[p], bBase + p * (16 * SMA * 2) + ks * 32);
#pragma unroll
        for (int mi = 0; mi < 4; mi++)
#pragma unroll
            for (int ni = 0; ni < 4; ni++) {
                int p = ni >> 1, s = (ni & 1) * 2;
                mma_bf16(acc[mi][ni], a[mi][0], a[mi][1], a[mi][2], a[mi][3],
                         b[p][s], b[p][s + 1]);
            }
    }
}

#define CPA16(dst, src) \
    asm volatile("cp.async.cg.shared.global [%0], [%1], 16;" :: "r"(dst), "l"(src))
#define CPA_COMMIT() asm volatile("cp.async.commit_group;" ::: "memory")
#define CPA_WAIT0()  asm volatile("cp.async.wait_group 0;" ::: "memory")

// ---------------- 1) w_res = w - U @ V ----------------
__global__ void k_wres(const float* __restrict__ w, const float* __restrict__ U,
                       const float* __restrict__ V) {
    int o = blockIdx.x;
    __shared__ float u[TR];
    if (threadIdx.x < TR) u[threadIdx.x] = U[o * TR + threadIdx.x];
    __syncthreads();
    for (int c = threadIdx.x; c < TC; c += 256) {
        float acc = w[(size_t)o * TC + c];
#pragma unroll
        for (int r = 0; r < TR; r++) acc = __fmaf_rn(-u[r], V[r * TC + c], acc);
        g_wres[(size_t)o * TC + c] = acc;
    }
}

// ------- 2) weight rotate (Kahan fp32) + static quant -> bf16 codes -------
__global__ void __launch_bounds__(256) k_wrotq(const float* __restrict__ R0,
                                               const float* __restrict__ R1,
                                               const float* __restrict__ ws0,
                                               const float* __restrict__ ws1) {
    int half = blockIdx.y;
    const float* R = half ? R1 : R0;
    const float* ws = half ? ws1 : ws0;
    int o0 = blockIdx.x * 4;
    __shared__ float wr[4][TH];
    for (int i = threadIdx.x; i < 4 * TH; i += 256)
        wr[i >> 9][i & 511] = g_wres[(size_t)(o0 + (i >> 9)) * TC + half * TH + (i & 511)];
    __syncthreads();
    int n = threadIdx.x;
    float s[4][2] = {}, c[4][2] = {};
    for (int k = 0; k < TH; k++) {
        float b0 = R[k * TH + n], b1 = R[k * TH + n + 256];
#pragma unroll
        for (int i = 0; i < 4; i++) {
            float a = wr[i][k];
            float p0 = __fmul_rn(a, b0);
            float y0 = __fadd_rn(p0, -c[i][0]);
            float t0 = __fadd_rn(s[i][0], y0);
            c[i][0] = __fadd_rn(__fadd_rn(t0, -s[i][0]), -y0);
            s[i][0] = t0;
            float p1 = __fmul_rn(a, b1);
            float y1 = __fadd_rn(p1, -c[i][1]);
            float t1 = __fadd_rn(s[i][1], y1);
            c[i][1] = __fadd_rn(__fadd_rn(t1, -s[i][1]), -y1);
            s[i][1] = t1;
        }
    }
#pragma unroll
    for (int i = 0; i < 4; i++) {
        float sw = ws[o0 + i];
        g_qwb[(size_t)(o0 + i) * TC + half * TH + n]       = __float2bfloat16_rn(qcode(s[i][0], sw));
        g_qwb[(size_t)(o0 + i) * TC + half * TH + n + 256] = __float2bfloat16_rn(qcode(s[i][1], sw));
    }
}

// -------- 2b) pre-split R (transposed) --------
__global__ void k_rsplit(const float* __restrict__ R0, const float* __restrict__ R1) {
    int half = blockIdx.y, n = blockIdx.x;
    const float* R = half ? R1 : R0;
    size_t ob = (size_t)half * TH * TH + (size_t)n * TH;
    for (int k = threadIdx.x; k < TH; k += 256) {
        float v = R[(size_t)k * TH + n];
        __nv_bfloat16 h = __float2bfloat16_rn(v);
        g_rh[ob + k] = h;
        g_rm[ob + k] = __float2bfloat16_rn(v - __bfloat162float(h));
    }
}

// -------- 2c) pre-split x --------
__global__ void __launch_bounds__(256) k_xsplit(const float* __restrict__ x) {
    size_t base = ((size_t)blockIdx.x * 256 + threadIdx.x) * 16;
    __nv_bfloat16 h16[16], m16[16];
#pragma unroll
    for (int j = 0; j < 4; j++) {
        float4 v = *(const float4*)(x + base + j * 4);
        float vv[4] = {v.x, v.y, v.z, v.w};
#pragma unroll
        for (int q = 0; q < 4; q++) {
            __nv_bfloat16 h = __float2bfloat16_rn(vv[q]);
            h16[j * 4 + q] = h;
            m16[j * 4 + q] = __float2bfloat16_rn(vv[q] - __bfloat162float(h));
        }
    }
    *(uint4*)&g_xh[base]     = *(uint4*)&h16[0];
    *(uint4*)&g_xh[base + 8] = *(uint4*)&h16[8];
    *(uint4*)&g_xm[base]     = *(uint4*)&m16[0];
    *(uint4*)&g_xm[base + 8] = *(uint4*)&m16[8];
}

// ------- 3) x rotation: bf16 HMMA, 3 passes, double-buffered cp.async, 2 CTAs/SM -------
#define XBUFB (128 * SMA * 2)   // bytes per operand array (10240)

__global__ void __launch_bounds__(256, 2) k_xrot() {
    extern __shared__ __align__(16) char xsm[];
    const int half = blockIdx.z;
    const int n0 = blockIdx.x * 128, m0 = blockIdx.y * 128;
    const int tid = threadIdx.x, lane = tid & 31, wid = tid >> 5;
    const int wm = wid >> 2, wn = wid & 3;
    uint32_t sbase = (uint32_t)__cvta_generic_to_shared(xsm);

    float acc[4][4][4];
#pragma unroll
    for (int i = 0; i < 4; i++)
#pragma unroll
        for (int j = 0; j < 4; j++)
#pragma unroll
            for (int c = 0; c < 4; c++) acc[i][j][c] = 0.0f;

    const int g = lane >> 3, r = lane & 7;
    uint32_t aoff = (uint32_t)(((wm * 64 + (g & 1) * 8 + r) * SMA + (g >> 1) * 8) * 2);
    uint32_t boff = (uint32_t)(((wn * 32 + (g >> 1) * 8 + r) * SMA + (g & 1) * 8) * 2);

    const int srow = tid >> 1, skq = (tid & 1) * 16;
    const uint32_t stoff = (uint32_t)((srow * SMA + skq) * 2);
    const __nv_bfloat16* Axh = g_xh + (size_t)(m0 + srow) * TC + half * TH + skq;
    const __nv_bfloat16* Axm = g_xm + (size_t)(m0 + srow) * TC + half * TH + skq;
    const __nv_bfloat16* Brh = g_rh + (size_t)half * TH * TH + (size_t)(n0 + srow) * TH + skq;
    const __nv_bfloat16* Brm = g_rm + (size_t)half * TH * TH + (size_t)(n0 + srow) * TH + skq;

    auto issue = [&](int buf, int k0) {
        uint32_t b = sbase + (uint32_t)buf * (4 * XBUFB) + stoff;
        CPA16(b,                  Axh + k0);
        CPA16(b + 16,             Axh + k0 + 8);
        CPA16(b + XBUFB,          Axm + k0);
        CPA16(b + XBUFB + 16,     Axm + k0 + 8);
        CPA16(b + 2 * XBUFB,      Brh + k0);
        CPA16(b + 2 * XBUFB + 16, Brh + k0 + 8);
        CPA16(b + 3 * XBUFB,      Brm + k0);
        CPA16(b + 3 * XBUFB + 16, Brm + k0 + 8);
        CPA_COMMIT();
    };

    issue(0, 0);
    for (int it = 0; it < 16; it++) {
        CPA_WAIT0();
        __syncthreads();
        if (it < 15) issue((it + 1) & 1, (it + 1) * 32);
        uint32_t bb = sbase + (uint32_t)(it & 1) * (4 * XBUFB);
        mm_compute(bb + aoff, bb + 3 * XBUFB + boff, acc);              // h*m
        mm_compute(bb + XBUFB + aoff, bb + 2 * XBUFB + boff, acc);      // m*h
        mm_compute(bb + aoff, bb + 2 * XBUFB + boff, acc);              // h*h
    }

    const int qrow = lane >> 2, qcol = (lane & 3) * 2;
#pragma unroll
    for (int mi = 0; mi < 4; mi++) {
        size_t row = m0 + wm * 64 + mi * 16 + qrow;
#pragma unroll
        for (int ni = 0; ni < 4; ni++) {
            int col = half * TH + n0 + wn * 32 + ni * 8 + qcol;
            *(float2*)&g_x[row * TC + col] = make_float2(acc[mi][ni][0], acc[mi][ni][1]);
            *(float2*)&g_x[(row + 8) * TC + col] = make_float2(acc[mi][ni][2], acc[mi][ni][3]);
        }
    }
}

// ------- 4) p = x @ V^T via bf16 3-pass MMA, 2 CTAs/SM -------
__global__ void __launch_bounds__(256, 2) k_p(const float* __restrict__ V) {
    __shared__ __align__(16) __nv_bfloat16 Ah[128 * SMA], Am[128 * SMA];
    __shared__ __align__(16) __nv_bfloat16 Bh[32 * SMA], Bm[32 * SMA];
    const int m0 = blockIdx.x * 128;
    const int tid = threadIdx.x, lane = tid & 31, wid = tid >> 5;

    float acc[4][4];
#pragma unroll
    for (int i = 0; i < 4; i++)
#pragma unroll
        for (int c = 0; c < 4; c++) acc[i][c] = 0.0f;

    const int g = lane >> 3, r = lane & 7;
    uint32_t smAh = (uint32_t)__cvta_generic_to_shared(Ah);
    uint32_t smAm = (uint32_t)__cvta_generic_to_shared(Am);
    uint32_t smBh = (uint32_t)__cvta_generic_to_shared(Bh);
    uint32_t smBm = (uint32_t)__cvta_generic_to_shared(Bm);
    uint32_t aoff = (uint32_t)(((wid * 16 + (g & 1) * 8 + r) * SMA + (g >> 1) * 8) * 2);
    uint32_t boff = (uint32_t)((((g >> 1) * 8 + r) * SMA + (g & 1) * 8) * 2);

    const int srow = tid >> 1, skq = (tid & 1) * 16;
    const __nv_bfloat16* Axh = g_xh + (size_t)(m0 + srow) * TC + skq;
    const __nv_bfloat16* Axm = g_xm + (size_t)(m0 + srow) * TC + skq;
    const int vr = tid >> 3, vkq = (tid & 7) * 4;
    const float* Vg = V + (size_t)vr * TC + vkq;

    uint4 a0 = *(const uint4*)Axh, a1 = *(const uint4*)(Axh + 8);
    uint4 a2 = *(const uint4*)Axm, a3 = *(const uint4*)(Axm + 8);
    float4 bv = *(const float4*)Vg;

    for (int it = 0; it < 32; it++) {
        *(uint4*)&Ah[srow * SMA + skq]     = a0;
        *(uint4*)&Ah[srow * SMA + skq + 8] = a1;
        *(uint4*)&Am[srow * SMA + skq]     = a2;
        *(uint4*)&Am[srow * SMA + skq + 8] = a3;
        {
            float vv[4] = {bv.x, bv.y, bv.z, bv.w};
            __nv_bfloat16 h4[4], m4[4];
#pragma unroll
            for (int q = 0; q < 4; q++) {
                __nv_bfloat16 h = __float2bfloat16_rn(vv[q]);
                h4[q] = h;
                m4[q] = __float2bfloat16_rn(vv[q] - __bfloat162float(h));
            }
            *(uint2*)&Bh[vr * SMA + vkq] = *(uint2*)h4;
            *(uint2*)&Bm[vr * SMA + vkq] = *(uint2*)m4;
        }
        __syncthreads();
        if (it < 31) {
            int k0 = (it + 1) * 32;
            a0 = *(const uint4*)(Axh + k0);  a1 = *(const uint4*)(Axh + k0 + 8);
            a2 = *(const uint4*)(Axm + k0);  a3 = *(const uint4*)(Axm + k0 + 8);
            bv = *(const float4*)(Vg + k0);
        }
#pragma unroll 1
        for (int pass = 0; pass < 3; pass++) {
            uint32_t aB = (pass == 1) ? smAm + aoff : smAh + aoff;
            uint32_t bB = (pass == 0) ? smBm + boff : smBh + boff;
#pragma unroll
            for (int ks = 0; ks < 2; ks++) {
                uint32_t a[4], b[2][4];
                ldsm4(a, aB + ks * 32);
                ldsm4(b[0], bB + ks * 32);
                ldsm4(b[1], bB + 16 * SMA * 2 + ks * 32);
#pragma unroll
                for (int ni = 0; ni < 4; ni++) {
                    int p = ni >> 1, s = (ni & 1) * 2;
                    mma_bf16(acc[ni], a[0], a[1], a[2], a[3], b[p][s], b[p][s + 1]);
                }
            }
        }
        __syncthreads();
    }

    const int qrow = lane >> 2, qcol = (lane & 3) * 2;
#pragma unroll
    for (int ni = 0; ni < 4; ni++) {
        size_t row = m0 + wid * 16 + qrow;
        int col = ni * 8 + qcol;
        *(float2*)&g_p[row * TR + col]       = make_float2(acc[ni][0], acc[ni][1]);
        *(float2*)&g_p[(row + 8) * TR + col] = make_float2(acc[ni][2], acc[ni][3]);
    }
}

// -------- 5a) zero flag counter --------
__global__ void k_zero() { g_flagcnt = 0; }

// -------- 5b) dynamic quant: warp-per-half-token, shfl-only reduction --------
__global__ void __launch_bounds__(256) k_quant() {
    int wid = threadIdx.x >> 5, lane = threadIdx.x & 31;
    size_t t = (size_t)blockIdx.x * 4 + (wid >> 1);
    int half = wid & 1;
    const float* xr = g_x + t * TC + half * TH;

    float4 v[4];
    float m = 0.0f;
    int mi = 0;
#pragma unroll
    for (int j = 0; j < 4; j++) {
        int base = lane * 4 + j * 128;
        v[j] = *(const float4*)(xr + base);
        float a[4] = {fabsf(v[j].x), fabsf(v[j].y), fabsf(v[j].z), fabsf(v[j].w)};
#pragma unroll
        for (int q = 0; q < 4; q++)
            if (a[q] > m || (a[q] == m && base + q < mi)) { m = a[q]; mi = base + q; }
    }
#pragma unroll
    for (int o = 16; o; o >>= 1) {
        float om = __shfl_xor_sync(0xffffffffu, m, o);
        int   oi = __shfl_xor_sync(0xffffffffu, mi, o);
        if (om > m || (om == m && oi < mi)) { m = om; mi = oi; }
    }
    float s = fmaxf(__fdiv_rn(m, 7.0f), 1e-8f);
    if (lane == 0) {
        if (half) g_s1[t] = s; else g_s0[t] = s;
        g_aidx[t * 2 + half] = mi;
    }

    __nv_bfloat16* qr = g_qx + t * TC + half * TH;
#pragma unroll
    for (int j = 0; j < 4; j++) {
        int base = lane * 4 + j * 128;
        float vv[4] = {v[j].x, v[j].y, v[j].z, v[j].w};
        __nv_bfloat16 cd[4];
#pragma unroll
        for (int q = 0; q < 4; q++) {
            float u = __fdiv_rn(vv[q], s);
            float rr = rintf(u);
            cd[q] = __float2bfloat16_rn(fminf(fmaxf(rr, -8.0f), 7.0f));
            if (0.5f - fabsf(u - rr) < TAU) {
                int idx = atomicAdd(&g_flagcnt, 1);
                if (idx < FCAP) g_flags[idx] = ((int)t << 10) | (half * TH + base + q);
            }
        }
        *(uint2*)(qr + base) = *(uint2*)cd;
    }
}

// -------- 5c) fix-up: warp-cooperative exact serial fp32 chain --------
// One warp per flag. Lanes cooperatively load 32 consecutive k-elements
// (xr coalesced; R columns 32-way MLP), then ALL lanes redundantly run the
// bit-identical k-ascending fma.rn chain with shfl-broadcast operands.
__global__ void __launch_bounds__(256) k_fix(const float* __restrict__ x,
                                             const float* __restrict__ R0,
                                             const float* __restrict__ R1) {
    int cnt = g_flagcnt;
    if (cnt > FCAP) cnt = FCAP;
    int lane = threadIdx.x & 31;
    int warpId = (blockIdx.x * blockDim.x + threadIdx.x) >> 5;
    int nWarps = (gridDim.x * blockDim.x) >> 5;

    for (int i = warpId; i < cnt; i += nWarps) {
        int e = g_flags[i];
        int t = e >> 10, c = e & 1023;
        int h = c >> 9, cc = c & 511;
        const float* xr = x + (size_t)t * TC + h * TH;
        const float* R = h ? R1 : R0;
        int ac = g_aidx[t * 2 + h];

        float v = 0.0f, va = 0.0f;
#pragma unroll 1
        for (int kb = 0; kb < TH; kb += 32) {
            int k = kb + lane;
            float xv = xr[k];
            float r1 = R[(size_t)k * TH + cc];
            float r2 = R[(size_t)k * TH + ac];
#pragma unroll
            for (int j = 0; j < 32; j++) {
                float xj  = __shfl_sync(0xffffffffu, xv, j);
                float r1j = __shfl_sync(0xffffffffu, r1, j);
                float r2j = __shfl_sync(0xffffffffu, r2, j);
                v  = __fmaf_rn(xj, r1j, v);
                va = __fmaf_rn(xj, r2j, va);
            }
        }
        if (lane == 0) {
            float s = fmaxf(__fdiv_rn(fabsf(va), 7.0f), 1e-8f);
            g_qx[(size_t)t * TC + c] = __float2bfloat16_rn(qcode(v, s));
        }
    }
}

// -------- 6) main GEMM: bf16 HMMA on integer codes + fused skip/affine, 2 CTAs/SM --------
__global__ void __launch_bounds__(256, 2) k_main(const float* __restrict__ U,
                                                 const float* __restrict__ bias,
                                                 const float* __restrict__ ws0,
                                                 const float* __restrict__ ws1,
                                                 const float* __restrict__ gamma,
                                                 const float* __restrict__ beta,
                                                 float* __restrict__ out) {
    __shared__ __align__(16) __nv_bfloat16 As[128 * SMA];
    __shared__ __align__(16) __nv_bfloat16 Bs[128 * SMA];
    const int tid = threadIdx.x;
    const int lane = tid & 31, wid = tid >> 5;
    const int wm = wid >> 2, wn = wid & 3;
    const int n0 = blockIdx.x * 128, m0 = blockIdx.y * 128;

    float acc[4][4][4];
#pragma unroll
    for (int i = 0; i < 4; i++)
#pragma unroll
        for (int j = 0; j < 4; j++)
#pragma unroll
            for (int c = 0; c < 4; c++) acc[i][j][c] = 0.0f;

    const int g = lane >> 3, r = lane & 7;
    uint32_t smA = (uint32_t)__cvta_generic_to_shared(As);
    uint32_t smB = (uint32_t)__cvta_generic_to_shared(Bs);
    uint32_t aBase = smA + (uint32_t)(((wm * 64 + (g & 1) * 8 + r) * SMA + (g >> 1) * 8) * 2);
    uint32_t bBase = smB + (uint32_t)(((wn * 32 + (g >> 1) * 8 + r) * SMA + (g & 1) * 8) * 2);

    const int lrow = tid >> 2, lq = (tid & 3) * 8;
    const __nv_bfloat16* Ag = g_qx + (size_t)m0 * TC;
    const __nv_bfloat16* Bg = g_qwb + (size_t)n0 * TC;

    uint4 av0, av1, bv0, bv1;
    av0 = *(const uint4*)(Ag + (size_t)lrow * TC + lq);
    av1 = *(const uint4*)(Ag + (size_t)(lrow + 64) * TC + lq);
    bv0 = *(const uint4*)(Bg + (size_t)lrow * TC + lq);
    bv1 = *(const uint4*)(Bg + (size_t)(lrow + 64) * TC + lq);
    *(uint4*)&As[lrow * SMA + lq] = av0;
    *(uint4*)&As[(lrow + 64) * SMA + lq] = av1;
    *(uint4*)&Bs[lrow * SMA + lq] = bv0;
    *(uint4*)&Bs[(lrow + 64) * SMA + lq] = bv1;
    __syncthreads();

    const int qrow = lane >> 2, qcol = (lane & 3) * 2;

    for (int it = 0; it < 32; it++) {
        if (it < 31) {
            int k0 = (it + 1) * 32;
            av0 = *(const uint4*)(Ag + (size_t)lrow * TC + k0 + lq);
            av1 = *(const uint4*)(Ag + (size_t)(lrow + 64) * TC + k0 + lq);
            bv0 = *(const uint4*)(Bg + (size_t)lrow * TC + k0 + lq);
            bv1 = *(const uint4*)(Bg + (size_t)(lrow + 64) * TC + k0 + lq);
        }
        mm_compute(aBase, bBase, acc);
        if (it == 15) {
            float rr[4][2], rc[4][2];
#pragma unroll
            for (int mi = 0; mi < 4; mi++) {
                int rw = m0 + wm * 64 + mi * 16 + qrow;
                rr[mi][0] = __fdiv_rn(g_s0[rw], g_s1[rw]);
                rr[mi][1] = __fdiv_rn(g_s0[rw + 8], g_s1[rw + 8]);
            }
#pragma unroll
            for (int ni = 0; ni < 4; ni++) {
                int cl = n0 + wn * 32 + ni * 8 + qcol;
                rc[ni][0] = __fdiv_rn(ws0[cl], ws1[cl]);
                rc[ni][1] = __fdiv_rn(ws0[cl + 1], ws1[cl + 1]);
            }
#pragma unroll
            for (int mi = 0; mi < 4; mi++)
#pragma unroll
                for (int ni = 0; ni < 4; ni++) {
                    acc[mi][ni][0] *= rr[mi][0] * rc[ni][0];
                    acc[mi][ni][1] *= rr[mi][0] * rc[ni][1];
                    acc[mi][ni][2] *= rr[mi][1] * rc[ni][0];
                    acc[mi][ni][3] *= rr[mi][1] * rc[ni][1];
                }
        }
        __syncthreads();
        if (it < 31) {
            *(uint4*)&As[lrow * SMA + lq] = av0;
            *(uint4*)&As[(lrow + 64) * SMA + lq] = av1;
            *(uint4*)&Bs[lrow * SMA + lq] = bv0;
            *(uint4*)&Bs[(lrow + 64) * SMA + lq] = bv1;
            __syncthreads();
        }
    }

    {
        float sr[4][2], sc[4][2];
#pragma unroll
        for (int mi = 0; mi < 4; mi++) {
            int rw = m0 + wm * 64 + mi * 16 + qrow;
            sr[mi][0] = g_s1[rw];
            sr[mi][1] = g_s1[rw + 8];
        }
#pragma unroll
        for (int ni = 0; ni < 4; ni++) {
            int cl = n0 + wn * 32 + ni * 8 + qcol;
            sc[ni][0] = ws1[cl];
            sc[ni][1] = ws1[cl + 1];
        }
#pragma unroll
        for (int mi = 0; mi < 4; mi++)
#pragma unroll
            for (int ni = 0; ni < 4; ni++) {
                acc[mi][ni][0] *= sr[mi][0] * sc[ni][0];
                acc[mi][ni][1] *= sr[mi][0] * sc[ni][1];
                acc[mi][ni][2] *= sr[mi][1] * sc[ni][0];
                acc[mi][ni][3] *= sr[mi][1] * sc[ni][1];
            }
    }

#pragma unroll 1
    for (int pass = 0; pass < 3; pass++) {
        __syncthreads();
#pragma unroll
        for (int l = 0; l < 16; l++) {
            int idx = tid + l * 256, row = idx >> 5, c = idx & 31;
            if (pass != 1) {
                float v = g_p[(size_t)(m0 + row) * TR + c];
                __nv_bfloat16 h = __float2bfloat16_rn(v);
                As[row * SMA + c] =
                    (pass == 2) ? __float2bfloat16_rn(v - __bfloat162float(h)) : h;
            }
            {
                float v = U[(size_t)(n0 + row) * TR + c];
                __nv_bfloat16 h = __float2bfloat16_rn(v);
                Bs[row * SMA + c] =
                    (pass == 1) ? __float2bfloat16_rn(v - __bfloat162float(h)) : h;
            }
        }
        __syncthreads();
        mm_compute(aBase, bBase, acc);
    }

    float bi[4][2], ga[4][2], be[4][2];
#pragma unroll
    for (int ni = 0; ni < 4; ni++) {
        int cl = n0 + wn * 32 + ni * 8 + qcol;
        bi[ni][0] = bias[cl];  bi[ni][1] = bias[cl + 1];
        ga[ni][0] = gamma[cl]; ga[ni][1] = gamma[cl + 1];
        be[ni][0] = beta[cl];  be[ni][1] = beta[cl + 1];
    }
#pragma unroll
    for (int mi = 0; mi < 4; mi++) {
        size_t r0 = m0 + wm * 64 + mi * 16 + qrow;
#pragma unroll
        for (int ni = 0; ni < 4; ni++) {
            int cl = n0 + wn * 32 + ni * 8 + qcol;
            float2 o0, o1;
            o0.x = __fmaf_rn(acc[mi][ni][0] + bi[ni][0], ga[ni][0], be[ni][0]);
            o0.y = __fmaf_rn(acc[mi][ni][1] + bi[ni][1], ga[ni][1], be[ni][1]);
            o1.x = __fmaf_rn(acc[mi][ni][2] + bi[ni][0], ga[ni][0], be[ni][0]);
            o1.y = __fmaf_rn(acc[mi][ni][3] + bi[ni][1], ga[ni][1], be[ni][1]);
            *(float2*)&out[r0 * TO + cl] = o0;
            *(float2*)&out[(r0 + 8) * TO + cl] = o1;
        }
    }
}

extern "C" void kernel_launch(void* const* d_in, const int* in_sizes, int n_in,
                              void* d_out, int out_size) {
    const float* x     = (const float*)d_in[0];
    const float* w     = (const float*)d_in[1];
    const float* bias  = (const float*)d_in[2];
    const float* U     = (const float*)d_in[3];
    const float* V     = (const float*)d_in[4];
    const float* R0    = (const float*)d_in[5];
    const float* R1    = (const float*)d_in[6];
    const float* ws0   = (const float*)d_in[7];
    const float* ws1   = (const float*)d_in[8];
    const float* gamma = (const float*)d_in[9];
    const float* beta  = (const float*)d_in[10];
    float* out = (float*)d_out;

    cudaFuncSetAttribute(k_xrot, cudaFuncAttributeMaxDynamicSharedMemorySize,
                         8 * XBUFB);

    k_wres<<<TO, 256>>>(w, U, V);
    k_wrotq<<<dim3(256, 2), 256>>>(R0, R1, ws0, ws1);
    k_rsplit<<<dim3(TH, 2), 256>>>(R0, R1);
    k_xsplit<<<(int)(((size_t)MT * TC) / (256 * 16)), 256>>>(x);
    k_xrot<<<dim3(4, 256, 2), 256, 8 * XBUFB>>>();
    k_p<<<256, 256>>>(V);
    k_zero<<<1, 1>>>();
    k_quant<<<MT / 4, 256>>>();
    k_fix<<<592, 256>>>(x, R0, R1);
    k_main<<<dim3(8, 256), 256>>>(U, bias, ws0, ws1, gamma, beta, out);
}

// round 16
// speedup vs baseline: 1.2505x; 1.2505x over previous
#include <cuda_runtime.h>
#include <cuda_bf16.h>
#include <cstdint>

#define MT 32768
#define TC 1024
#define TH 512
#define TO 1024
#define TR 32
#define FCAP (1 << 22)
#define TAU 6e-4f

__device__ float g_wres[(size_t)TO * TC];
__device__ __nv_bfloat16 g_qwb[(size_t)TO * TC];
__device__ float g_x[(size_t)MT * TC];               // rotated activations
__device__ __nv_bfloat16 g_qx[(size_t)MT * TC];      // activation codes
__device__ __nv_bfloat16 g_xh[(size_t)MT * TC];      // x split hi (bf16)
__device__ __nv_bfloat16 g_xm[(size_t)MT * TC];      // x split residual (bf16)
__device__ __nv_bfloat16 g_rh[2 * TH * TH];          // R^T split hi   [half][n][k]
__device__ __nv_bfloat16 g_rm[2 * TH * TH];          // R^T split res
__device__ float g_rt[2 * TH * TH];                  // R^T fp32 [half][n][k] (for k_fix)
__device__ float g_s0[MT];
__device__ float g_s1[MT];
__device__ float g_p[(size_t)MT * TR];
__device__ int g_flagcnt;
__device__ int g_flags[FCAP];
__device__ int g_aidx[MT * 2];

__device__ __forceinline__ float qcode(float v, float s) {
    float q = rintf(__fdiv_rn(v, s));
    return fminf(fmaxf(q, -8.0f), 7.0f);
}

// ---- shared MMA helpers (bf16 m16n8k16, ldmatrix, [row][k] smem, stride SMA) ----
#define SMA 40

__device__ __forceinline__ void mma_bf16(float* c, uint32_t a0, uint32_t a1,
                                         uint32_t a2, uint32_t a3,
                                         uint32_t b0, uint32_t b1) {
    asm volatile(
        "mma.sync.aligned.m16n8k16.row.col.f32.bf16.bf16.f32 "
        "{%0,%1,%2,%3}, {%4,%5,%6,%7}, {%8,%9}, {%0,%1,%2,%3};"
        : "+f"(c[0]), "+f"(c[1]), "+f"(c[2]), "+f"(c[3])
        : "r"(a0), "r"(a1), "r"(a2), "r"(a3), "r"(b0), "r"(b1));
}

__device__ __forceinline__ void ldsm4(uint32_t* r, uint32_t addr) {
    asm volatile("ldmatrix.sync.aligned.m8n8.x4.shared.b16 {%0,%1,%2,%3}, [%4];"
                 : "=r"(r[0]), "=r"(r[1]), "=r"(r[2]), "=r"(r[3]) : "r"(addr));
}

__device__ __forceinline__ void mm_compute(uint32_t aBase, uint32_t bBase,
                                           float (&acc)[4][4][4]) {
#pragma unroll
    for (int ks = 0; ks < 2; ks++) {
        uint32_t a[4][4], b[2][4];
#pragma unroll
        for (int mi = 0; mi < 4; mi++) ldsm4(a[mi], aBase + mi * (16 * SMA * 2) + ks * 32);
#pragma unroll
        for (int p = 0; p < 2; p++) ldsm4(b[p], bBase + p * (16 * SMA * 2) + ks * 32);
#pragma unroll
        for (int mi = 0; mi < 4; mi++)
#pragma unroll
            for (int ni = 0; ni < 4; ni++) {
                int p = ni >> 1, s = (ni & 1) * 2;
                mma_bf16(acc[mi][ni], a[mi][0], a[mi][1], a[mi][2], a[mi][3],
                         b[p][s], b[p][s + 1]);
            }
    }
}

#define CPA16(dst, src) \
    asm volatile("cp.async.cg.shared.global [%0], [%1], 16;" :: "r"(dst), "l"(src))
#define CPA_COMMIT() asm volatile("cp.async.commit_group;" ::: "memory")
#define CPA_WAIT0()  asm volatile("cp.async.wait_group 0;" ::: "memory")

// ---------------- 1) w_res = w - U @ V ----------------
__global__ void k_wres(const float* __restrict__ w, const float* __restrict__ U,
                       const float* __restrict__ V) {
    int o = blockIdx.x;
    __shared__ float u[TR];
    if (threadIdx.x < TR) u[threadIdx.x] = U[o * TR + threadIdx.x];
    __syncthreads();
    for (int c = threadIdx.x; c < TC; c += 256) {
        float acc = w[(size_t)o * TC + c];
#pragma unroll
        for (int r = 0; r < TR; r++) acc = __fmaf_rn(-u[r], V[r * TC + c], acc);
        g_wres[(size_t)o * TC + c] = acc;
    }
}

// ------- 2) weight rotate (Kahan fp32) + static quant -> bf16 codes -------
__global__ void __launch_bounds__(256) k_wrotq(const float* __restrict__ R0,
                                               const float* __restrict__ R1,
                                               const float* __restrict__ ws0,
                                               const float* __restrict__ ws1) {
    int half = blockIdx.y;
    const float* R = half ? R1 : R0;
    const float* ws = half ? ws1 : ws0;
    int o0 = blockIdx.x * 4;
    __shared__ float wr[4][TH];
    for (int i = threadIdx.x; i < 4 * TH; i += 256)
        wr[i >> 9][i & 511] = g_wres[(size_t)(o0 + (i >> 9)) * TC + half * TH + (i & 511)];
    __syncthreads();
    int n = threadIdx.x;
    float s[4][2] = {}, c[4][2] = {};
    for (int k = 0; k < TH; k++) {
        float b0 = R[k * TH + n], b1 = R[k * TH + n + 256];
#pragma unroll
        for (int i = 0; i < 4; i++) {
            float a = wr[i][k];
            float p0 = __fmul_rn(a, b0);
            float y0 = __fadd_rn(p0, -c[i][0]);
            float t0 = __fadd_rn(s[i][0], y0);
            c[i][0] = __fadd_rn(__fadd_rn(t0, -s[i][0]), -y0);
            s[i][0] = t0;
            float p1 = __fmul_rn(a, b1);
            float y1 = __fadd_rn(p1, -c[i][1]);
            float t1 = __fadd_rn(s[i][1], y1);
            c[i][1] = __fadd_rn(__fadd_rn(t1, -s[i][1]), -y1);
            s[i][1] = t1;
        }
    }
#pragma unroll
    for (int i = 0; i < 4; i++) {
        float sw = ws[o0 + i];
        g_qwb[(size_t)(o0 + i) * TC + half * TH + n]       = __float2bfloat16_rn(qcode(s[i][0], sw));
        g_qwb[(size_t)(o0 + i) * TC + half * TH + n + 256] = __float2bfloat16_rn(qcode(s[i][1], sw));
    }
}

// -------- 2b) pre-split R (transposed) + fp32 transpose for k_fix --------
__global__ void k_rsplit(const float* __restrict__ R0, const float* __restrict__ R1) {
    int half = blockIdx.y, n = blockIdx.x;
    const float* R = half ? R1 : R0;
    size_t ob = (size_t)half * TH * TH + (size_t)n * TH;
    for (int k = threadIdx.x; k < TH; k += 256) {
        float v = R[(size_t)k * TH + n];
        __nv_bfloat16 h = __float2bfloat16_rn(v);
        g_rh[ob + k] = h;
        g_rm[ob + k] = __float2bfloat16_rn(v - __bfloat162float(h));
        g_rt[ob + k] = v;
    }
}

// -------- 2c) pre-split x --------
__global__ void __launch_bounds__(256) k_xsplit(const float* __restrict__ x) {
    size_t base = ((size_t)blockIdx.x * 256 + threadIdx.x) * 16;
    __nv_bfloat16 h16[16], m16[16];
#pragma unroll
    for (int j = 0; j < 4; j++) {
        float4 v = *(const float4*)(x + base + j * 4);
        float vv[4] = {v.x, v.y, v.z, v.w};
#pragma unroll
        for (int q = 0; q < 4; q++) {
            __nv_bfloat16 h = __float2bfloat16_rn(vv[q]);
            h16[j * 4 + q] = h;
            m16[j * 4 + q] = __float2bfloat16_rn(vv[q] - __bfloat162float(h));
        }
    }
    *(uint4*)&g_xh[base]     = *(uint4*)&h16[0];
    *(uint4*)&g_xh[base + 8] = *(uint4*)&h16[8];
    *(uint4*)&g_xm[base]     = *(uint4*)&m16[0];
    *(uint4*)&g_xm[base + 8] = *(uint4*)&m16[8];
}

// ------- 3) x rotation: bf16 HMMA, 3 passes, double-buffered cp.async, 2 CTAs/SM -------
#define XBUFB (128 * SMA * 2)   // bytes per operand array (10240)

__global__ void __launch_bounds__(256, 2) k_xrot() {
    extern __shared__ __align__(16) char xsm[];
    const int half = blockIdx.z;
    const int n0 = blockIdx.x * 128, m0 = blockIdx.y * 128;
    const int tid = threadIdx.x, lane = tid & 31, wid = tid >> 5;
    const int wm = wid >> 2, wn = wid & 3;
    uint32_t sbase = (uint32_t)__cvta_generic_to_shared(xsm);

    float acc[4][4][4];
#pragma unroll
    for (int i = 0; i < 4; i++)
#pragma unroll
        for (int j = 0; j < 4; j++)
#pragma unroll
            for (int c = 0; c < 4; c++) acc[i][j][c] = 0.0f;

    const int g = lane >> 3, r = lane & 7;
    uint32_t aoff = (uint32_t)(((wm * 64 + (g & 1) * 8 + r) * SMA + (g >> 1) * 8) * 2);
    uint32_t boff = (uint32_t)(((wn * 32 + (g >> 1) * 8 + r) * SMA + (g & 1) * 8) * 2);

    const int srow = tid >> 1, skq = (tid & 1) * 16;
    const uint32_t stoff = (uint32_t)((srow * SMA + skq) * 2);
    const __nv_bfloat16* Axh = g_xh + (size_t)(m0 + srow) * TC + half * TH + skq;
    const __nv_bfloat16* Axm = g_xm + (size_t)(m0 + srow) * TC + half * TH + skq;
    const __nv_bfloat16* Brh = g_rh + (size_t)half * TH * TH + (size_t)(n0 + srow) * TH + skq;
    const __nv_bfloat16* Brm = g_rm + (size_t)half * TH * TH + (size_t)(n0 + srow) * TH + skq;

    auto issue = [&](int buf, int k0) {
        uint32_t b = sbase + (uint32_t)buf * (4 * XBUFB) + stoff;
        CPA16(b,                  Axh + k0);
        CPA16(b + 16,             Axh + k0 + 8);
        CPA16(b + XBUFB,          Axm + k0);
        CPA16(b + XBUFB + 16,     Axm + k0 + 8);
        CPA16(b + 2 * XBUFB,      Brh + k0);
        CPA16(b + 2 * XBUFB + 16, Brh + k0 + 8);
        CPA16(b + 3 * XBUFB,      Brm + k0);
        CPA16(b + 3 * XBUFB + 16, Brm + k0 + 8);
        CPA_COMMIT();
    };

    issue(0, 0);
    for (int it = 0; it < 16; it++) {
        CPA_WAIT0();
        __syncthreads();
        if (it < 15) issue((it + 1) & 1, (it + 1) * 32);
        uint32_t bb = sbase + (uint32_t)(it & 1) * (4 * XBUFB);
        mm_compute(bb + aoff, bb + 3 * XBUFB + boff, acc);              // h*m
        mm_compute(bb + XBUFB + aoff, bb + 2 * XBUFB + boff, acc);      // m*h
        mm_compute(bb + aoff, bb + 2 * XBUFB + boff, acc);              // h*h
    }

    const int qrow = lane >> 2, qcol = (lane & 3) * 2;
#pragma unroll
    for (int mi = 0; mi < 4; mi++) {
        size_t row = m0 + wm * 64 + mi * 16 + qrow;
#pragma unroll
        for (int ni = 0; ni < 4; ni++) {
            int col = half * TH + n0 + wn * 32 + ni * 8 + qcol;
            *(float2*)&g_x[row * TC + col] = make_float2(acc[mi][ni][0], acc[mi][ni][1]);
            *(float2*)&g_x[(row + 8) * TC + col] = make_float2(acc[mi][ni][2], acc[mi][ni][3]);
        }
    }
}

// ------- 4) p = x @ V^T via bf16 3-pass MMA, 2 CTAs/SM -------
__global__ void __launch_bounds__(256, 2) k_p(const float* __restrict__ V) {
    __shared__ __align__(16) __nv_bfloat16 Ah[128 * SMA], Am[128 * SMA];
    __shared__ __align__(16) __nv_bfloat16 Bh[32 * SMA], Bm[32 * SMA];
    const int m0 = blockIdx.x * 128;
    const int tid = threadIdx.x, lane = tid & 31, wid = tid >> 5;

    float acc[4][4];
#pragma unroll
    for (int i = 0; i < 4; i++)
#pragma unroll
        for (int c = 0; c < 4; c++) acc[i][c] = 0.0f;

    const int g = lane >> 3, r = lane & 7;
    uint32_t smAh = (uint32_t)__cvta_generic_to_shared(Ah);
    uint32_t smAm = (uint32_t)__cvta_generic_to_shared(Am);
    uint32_t smBh = (uint32_t)__cvta_generic_to_shared(Bh);
    uint32_t smBm = (uint32_t)__cvta_generic_to_shared(Bm);
    uint32_t aoff = (uint32_t)(((wid * 16 + (g & 1) * 8 + r) * SMA + (g >> 1) * 8) * 2);
    uint32_t boff = (uint32_t)((((g >> 1) * 8 + r) * SMA + (g & 1) * 8) * 2);

    const int srow = tid >> 1, skq = (tid & 1) * 16;
    const __nv_bfloat16* Axh = g_xh + (size_t)(m0 + srow) * TC + skq;
    const __nv_bfloat16* Axm = g_xm + (size_t)(m0 + srow) * TC + skq;
    const int vr = tid >> 3, vkq = (tid & 7) * 4;
    const float* Vg = V + (size_t)vr * TC + vkq;

    uint4 a0 = *(const uint4*)Axh, a1 = *(const uint4*)(Axh + 8);
    uint4 a2 = *(const uint4*)Axm, a3 = *(const uint4*)(Axm + 8);
    float4 bv = *(const float4*)Vg;

    for (int it = 0; it < 32; it++) {
        *(uint4*)&Ah[srow * SMA + skq]     = a0;
        *(uint4*)&Ah[srow * SMA + skq + 8] = a1;
        *(uint4*)&Am[srow * SMA + skq]     = a2;
        *(uint4*)&Am[srow * SMA + skq + 8] = a3;
        {
            float vv[4] = {bv.x, bv.y, bv.z, bv.w};
            __nv_bfloat16 h4[4], m4[4];
#pragma unroll
            for (int q = 0; q < 4; q++) {
                __nv_bfloat16 h = __float2bfloat16_rn(vv[q]);
                h4[q] = h;
                m4[q] = __float2bfloat16_rn(vv[q] - __bfloat162float(h));
            }
            *(uint2*)&Bh[vr * SMA + vkq] = *(uint2*)h4;
            *(uint2*)&Bm[vr * SMA + vkq] = *(uint2*)m4;
        }
        __syncthreads();
        if (it < 31) {
            int k0 = (it + 1) * 32;
            a0 = *(const uint4*)(Axh + k0);  a1 = *(const uint4*)(Axh + k0 + 8);
            a2 = *(const uint4*)(Axm + k0);  a3 = *(const uint4*)(Axm + k0 + 8);
            bv = *(const float4*)(Vg + k0);
        }
#pragma unroll 1
        for (int pass = 0; pass < 3; pass++) {
            uint32_t aB = (pass == 1) ? smAm + aoff : smAh + aoff;
            uint32_t bB = (pass == 0) ? smBm + boff : smBh + boff;
#pragma unroll
            for (int ks = 0; ks < 2; ks++) {
                uint32_t a[4], b[2][4];
                ldsm4(a, aB + ks * 32);
                ldsm4(b[0], bB + ks * 32);
                ldsm4(b[1], bB + 16 * SMA * 2 + ks * 32);
#pragma unroll
                for (int ni = 0; ni < 4; ni++) {
                    int p = ni >> 1, s = (ni & 1) * 2;
                    mma_bf16(acc[ni], a[0], a[1], a[2], a[3], b[p][s], b[p][s + 1]);
                }
            }
        }
        __syncthreads();
    }

    const int qrow = lane >> 2, qcol = (lane & 3) * 2;
#pragma unroll
    for (int ni = 0; ni < 4; ni++) {
        size_t row = m0 + wid * 16 + qrow;
        int col = ni * 8 + qcol;
        *(float2*)&g_p[row * TR + col]       = make_float2(acc[ni][0], acc[ni][1]);
        *(float2*)&g_p[(row + 8) * TR + col] = make_float2(acc[ni][2], acc[ni][3]);
    }
}

// -------- 5a) zero flag counter --------
__global__ void k_zero() { g_flagcnt = 0; }

// -------- 5b) dynamic quant: warp-per-half-token, shfl-only reduction --------
__global__ void __launch_bounds__(256) k_quant() {
    int wid = threadIdx.x >> 5, lane = threadIdx.x & 31;
    size_t t = (size_t)blockIdx.x * 4 + (wid >> 1);
    int half = wid & 1;
    const float* xr = g_x + t * TC + half * TH;

    float4 v[4];
    float m = 0.0f;
    int mi = 0;
#pragma unroll
    for (int j = 0; j < 4; j++) {
        int base = lane * 4 + j * 128;
        v[j] = *(const float4*)(xr + base);
        float a[4] = {fabsf(v[j].x), fabsf(v[j].y), fabsf(v[j].z), fabsf(v[j].w)};
#pragma unroll
        for (int q = 0; q < 4; q++)
            if (a[q] > m || (a[q] == m && base + q < mi)) { m = a[q]; mi = base + q; }
    }
#pragma unroll
    for (int o = 16; o; o >>= 1) {
        float om = __shfl_xor_sync(0xffffffffu, m, o);
        int   oi = __shfl_xor_sync(0xffffffffu, mi, o);
        if (om > m || (om == m && oi < mi)) { m = om; mi = oi; }
    }
    float s = fmaxf(__fdiv_rn(m, 7.0f), 1e-8f);
    if (lane == 0) {
        if (half) g_s1[t] = s; else g_s0[t] = s;
        g_aidx[t * 2 + half] = mi;
    }

    __nv_bfloat16* qr = g_qx + t * TC + half * TH;
#pragma unroll
    for (int j = 0; j < 4; j++) {
        int base = lane * 4 + j * 128;
        float vv[4] = {v[j].x, v[j].y, v[j].z, v[j].w};
        __nv_bfloat16 cd[4];
#pragma unroll
        for (int q = 0; q < 4; q++) {
            float u = __fdiv_rn(vv[q], s);
            float rr = rintf(u);
            cd[q] = __float2bfloat16_rn(fminf(fmaxf(rr, -8.0f), 7.0f));
            if (0.5f - fabsf(u - rr) < TAU) {
                int idx = atomicAdd(&g_flagcnt, 1);
                if (idx < FCAP) g_flags[idx] = ((int)t << 10) | (half * TH + base + q);
            }
        }
        *(uint2*)(qr + base) = *(uint2*)cd;
    }
}

// -------- 5c) fix-up: exact serial fp32 chain, CONTIGUOUS loads via R^T --------
// One thread per flag; x row and R^T rows are contiguous (full 32B-sector use).
// FMA chain is bit-identical to the reference-correlated k-ascending order.
__global__ void __launch_bounds__(256) k_fix(const float* __restrict__ x) {
    int cnt = g_flagcnt;
    if (cnt > FCAP) cnt = FCAP;
    for (int i = blockIdx.x * blockDim.x + threadIdx.x; i < cnt;
         i += gridDim.x * blockDim.x) {
        int e = g_flags[i];
        int t = e >> 10, c = e & 1023;
        int h = c >> 9, cc = c & 511;
        const float4* xr = (const float4*)(x + (size_t)t * TC + h * TH);
        const float4* rc = (const float4*)(g_rt + (size_t)h * TH * TH + (size_t)cc * TH);
        int ac = g_aidx[t * 2 + h];
        const float4* ra = (const float4*)(g_rt + (size_t)h * TH * TH + (size_t)ac * TH);
        float v = 0.0f, va = 0.0f;
#pragma unroll 4
        for (int k4 = 0; k4 < TH / 4; k4++) {
            float4 xv = xr[k4];
            float4 c4 = rc[k4];
            float4 a4 = ra[k4];
            v  = __fmaf_rn(xv.x, c4.x, v);  va = __fmaf_rn(xv.x, a4.x, va);
            v  = __fmaf_rn(xv.y, c4.y, v);  va = __fmaf_rn(xv.y, a4.y, va);
            v  = __fmaf_rn(xv.z, c4.z, v);  va = __fmaf_rn(xv.z, a4.z, va);
            v  = __fmaf_rn(xv.w, c4.w, v);  va = __fmaf_rn(xv.w, a4.w, va);
        }
        float s = fmaxf(__fdiv_rn(fabsf(va), 7.0f), 1e-8f);
        g_qx[(size_t)t * TC + c] = __float2bfloat16_rn(qcode(v, s));
    }
}

// -------- 6) main GEMM: bf16 HMMA on integer codes + fused skip/affine, 2 CTAs/SM --------
__global__ void __launch_bounds__(256, 2) k_main(const float* __restrict__ U,
                                                 const float* __restrict__ bias,
                                                 const float* __restrict__ ws0,
                                                 const float* __restrict__ ws1,
                                                 const float* __restrict__ gamma,
                                                 const float* __restrict__ beta,
                                                 float* __restrict__ out) {
    __shared__ __align__(16) __nv_bfloat16 As[128 * SMA];
    __shared__ __align__(16) __nv_bfloat16 Bs[128 * SMA];
    const int tid = threadIdx.x;
    const int lane = tid & 31, wid = tid >> 5;
    const int wm = wid >> 2, wn = wid & 3;
    const int n0 = blockIdx.x * 128, m0 = blockIdx.y * 128;

    float acc[4][4][4];
#pragma unroll
    for (int i = 0; i < 4; i++)
#pragma unroll
        for (int j = 0; j < 4; j++)
#pragma unroll
            for (int c = 0; c < 4; c++) acc[i][j][c] = 0.0f;

    const int g = lane >> 3, r = lane & 7;
    uint32_t smA = (uint32_t)__cvta_generic_to_shared(As);
    uint32_t smB = (uint32_t)__cvta_generic_to_shared(Bs);
    uint32_t aBase = smA + (uint32_t)(((wm * 64 + (g & 1) * 8 + r) * SMA + (g >> 1) * 8) * 2);
    uint32_t bBase = smB + (uint32_t)(((wn * 32 + (g >> 1) * 8 + r) * SMA + (g & 1) * 8) * 2);

    const int lrow = tid >> 2, lq = (tid & 3) * 8;
    const __nv_bfloat16* Ag = g_qx + (size_t)m0 * TC;
    const __nv_bfloat16* Bg = g_qwb + (size_t)n0 * TC;

    uint4 av0, av1, bv0, bv1;
    av0 = *(const uint4*)(Ag + (size_t)lrow * TC + lq);
    av1 = *(const uint4*)(Ag + (size_t)(lrow + 64) * TC + lq);
    bv0 = *(const uint4*)(Bg + (size_t)lrow * TC + lq);
    bv1 = *(const uint4*)(Bg + (size_t)(lrow + 64) * TC + lq);
    *(uint4*)&As[lrow * SMA + lq] = av0;
    *(uint4*)&As[(lrow + 64) * SMA + lq] = av1;
    *(uint4*)&Bs[lrow * SMA + lq] = bv0;
    *(uint4*)&Bs[(lrow + 64) * SMA + lq] = bv1;
    __syncthreads();

    const int qrow = lane >> 2, qcol = (lane & 3) * 2;

    for (int it = 0; it < 32; it++) {
        if (it < 31) {
            int k0 = (it + 1) * 32;
            av0 = *(const uint4*)(Ag + (size_t)lrow * TC + k0 + lq);
            av1 = *(const uint4*)(Ag + (size_t)(lrow + 64) * TC + k0 + lq);
            bv0 = *(const uint4*)(Bg + (size_t)lrow * TC + k0 + lq);
            bv1 = *(const uint4*)(Bg + (size_t)(lrow + 64) * TC + k0 + lq);
        }
        mm_compute(aBase, bBase, acc);
        if (it == 15) {
            float rr[4][2], rc[4][2];
#pragma unroll
            for (int mi = 0; mi < 4; mi++) {
                int rw = m0 + wm * 64 + mi * 16 + qrow;
                rr[mi][0] = __fdiv_rn(g_s0[rw], g_s1[rw]);
                rr[mi][1] = __fdiv_rn(g_s0[rw + 8], g_s1[rw + 8]);
            }
#pragma unroll
            for (int ni = 0; ni < 4; ni++) {
                int cl = n0 + wn * 32 + ni * 8 + qcol;
                rc[ni][0] = __fdiv_rn(ws0[cl], ws1[cl]);
                rc[ni][1] = __fdiv_rn(ws0[cl + 1], ws1[cl + 1]);
            }
#pragma unroll
            for (int mi = 0; mi < 4; mi++)
#pragma unroll
                for (int ni = 0; ni < 4; ni++) {
                    acc[mi][ni][0] *= rr[mi][0] * rc[ni][0];
                    acc[mi][ni][1] *= rr[mi][0] * rc[ni][1];
                    acc[mi][ni][2] *= rr[mi][1] * rc[ni][0];
                    acc[mi][ni][3] *= rr[mi][1] * rc[ni][1];
                }
        }
        __syncthreads();
        if (it < 31) {
            *(uint4*)&As[lrow * SMA + lq] = av0;
            *(uint4*)&As[(lrow + 64) * SMA + lq] = av1;
            *(uint4*)&Bs[lrow * SMA + lq] = bv0;
            *(uint4*)&Bs[(lrow + 64) * SMA + lq] = bv1;
            __syncthreads();
        }
    }

    {
        float sr[4][2], sc[4][2];
#pragma unroll
        for (int mi = 0; mi < 4; mi++) {
            int rw = m0 + wm * 64 + mi * 16 + qrow;
            sr[mi][0] = g_s1[rw];
            sr[mi][1] = g_s1[rw + 8];
        }
#pragma unroll
        for (int ni = 0; ni < 4; ni++) {
            int cl = n0 + wn * 32 + ni * 8 + qcol;
            sc[ni][0] = ws1[cl];
            sc[ni][1] = ws1[cl + 1];
        }
#pragma unroll
        for (int mi = 0; mi < 4; mi++)
#pragma unroll
            for (int ni = 0; ni < 4; ni++) {
                acc[mi][ni][0] *= sr[mi][0] * sc[ni][0];
                acc[mi][ni][1] *= sr[mi][0] * sc[ni][1];
                acc[mi][ni][2] *= sr[mi][1] * sc[ni][0];
                acc[mi][ni][3] *= sr[mi][1] * sc[ni][1];
            }
    }

#pragma unroll 1
    for (int pass = 0; pass < 3; pass++) {
        __syncthreads();
#pragma unroll
        for (int l = 0; l < 16; l++) {
            int idx = tid + l * 256, row = idx >> 5, c = idx & 31;
            if (pass != 1) {
                float v = g_p[(size_t)(m0 + row) * TR + c];
                __nv_bfloat16 h = __float2bfloat16_rn(v);
                As[row * SMA + c] =
                    (pass == 2) ? __float2bfloat16_rn(v - __bfloat162float(h)) : h;
            }
            {
                float v = U[(size_t)(n0 + row) * TR + c];
                __nv_bfloat16 h = __float2bfloat16_rn(v);
                Bs[row * SMA + c] =
                    (pass == 1) ? __float2bfloat16_rn(v - __bfloat162float(h)) : h;
            }
        }
        __syncthreads();
        mm_compute(aBase, bBase, acc);
    }

    float bi[4][2], ga[4][2], be[4][2];
#pragma unroll
    for (int ni = 0; ni < 4; ni++) {
        int cl = n0 + wn * 32 + ni * 8 + qcol;
        bi[ni][0] = bias[cl];  bi[ni][1] = bias[cl + 1];
        ga[ni][0] = gamma[cl]; ga[ni][1] = gamma[cl + 1];
        be[ni][0] = beta[cl];  be[ni][1] = beta[cl + 1];
    }
#pragma unroll
    for (int mi = 0; mi < 4; mi++) {
        size_t r0 = m0 + wm * 64 + mi * 16 + qrow;
#pragma unroll
        for (int ni = 0; ni < 4; ni++) {
            int cl = n0 + wn * 32 + ni * 8 + qcol;
            float2 o0, o1;
            o0.x = __fmaf_rn(acc[mi][ni][0] + bi[ni][0], ga[ni][0], be[ni][0]);
            o0.y = __fmaf_rn(acc[mi][ni][1] + bi[ni][1], ga[ni][1], be[ni][1]);
            o1.x = __fmaf_rn(acc[mi][ni][2] + bi[ni][0], ga[ni][0], be[ni][0]);
            o1.y = __fmaf_rn(acc[mi][ni][3] + bi[ni][1], ga[ni][1], be[ni][1]);
            *(float2*)&out[r0 * TO + cl] = o0;
            *(float2*)&out[(r0 + 8) * TO + cl] = o1;
        }
    }
}

extern "C" void kernel_launch(void* const* d_in, const int* in_sizes, int n_in,
                              void* d_out, int out_size) {
    const float* x     = (const float*)d_in[0];
    const float* w     = (const float*)d_in[1];
    const float* bias  = (const float*)d_in[2];
    const float* U     = (const float*)d_in[3];
    const float* V     = (const float*)d_in[4];
    const float* R0    = (const float*)d_in[5];
    const float* R1    = (const float*)d_in[6];
    const float* ws0   = (const float*)d_in[7];
    const float* ws1   = (const float*)d_in[8];
    const float* gamma = (const float*)d_in[9];
    const float* beta  = (const float*)d_in[10];
    float* out = (float*)d_out;

    cudaFuncSetAttribute(k_xrot, cudaFuncAttributeMaxDynamicSharedMemorySize,
                         8 * XBUFB);

    k_wres<<<TO, 256>>>(w, U, V);
    k_wrotq<<<dim3(256, 2), 256>>>(R0, R1, ws0, ws1);
    k_rsplit<<<dim3(TH, 2), 256>>>(R0, R1);
    k_xsplit<<<(int)(((size_t)MT * TC) / (256 * 16)), 256>>>(x);
    k_xrot<<<dim3(4, 256, 2), 256, 8 * XBUFB>>>();
    k_p<<<256, 256>>>(V);
    k_zero<<<1, 1>>>();
    k_quant<<<MT / 4, 256>>>();
    k_fix<<<512, 256>>>(x);
    k_main<<<dim3(8, 256), 256>>>(U, bias, ws0, ws1, gamma, beta, out);
}

// round 17
// speedup vs baseline: 1.3236x; 1.0584x over previous
#include <cuda_runtime.h>
#include <cuda_bf16.h>
#include <cstdint>

#define MT 32768
#define TC 1024
#define TH 512
#define TO 1024
#define TR 32
#define FCAP (1 << 22)
#define TAU 6e-4f

__device__ float g_wres[(size_t)TO * TC];
__device__ __nv_bfloat16 g_qwb[(size_t)TO * TC];
__device__ float g_x[(size_t)MT * TC];               // rotated activations
__device__ __nv_bfloat16 g_qx[(size_t)MT * TC];      // activation codes
__device__ __nv_bfloat16 g_xh[(size_t)MT * TC];      // x split hi (bf16)
__device__ __nv_bfloat16 g_xm[(size_t)MT * TC];      // x split residual (bf16)
__device__ __nv_bfloat16 g_rh[2 * TH * TH];          // R^T split hi   [half][n][k]
__device__ __nv_bfloat16 g_rm[2 * TH * TH];          // R^T split res
__device__ float g_rt[2 * TH * TH];                  // R^T fp32 [half][n][k] (for k_fix)
__device__ float g_s0[MT];
__device__ float g_s1[MT];
__device__ float g_p[(size_t)MT * TR];
__device__ int g_flagcnt;
__device__ int g_flags[FCAP];
__device__ int g_aidx[MT * 2];

__device__ __forceinline__ float qcode(float v, float s) {
    float q = rintf(__fdiv_rn(v, s));
    return fminf(fmaxf(q, -8.0f), 7.0f);
}

// ---- shared MMA helpers (bf16 m16n8k16, ldmatrix, [row][k] smem, stride SMA) ----
#define SMA 40

__device__ __forceinline__ void mma_bf16(float* c, uint32_t a0, uint32_t a1,
                                         uint32_t a2, uint32_t a3,
                                         uint32_t b0, uint32_t b1) {
    asm volatile(
        "mma.sync.aligned.m16n8k16.row.col.f32.bf16.bf16.f32 "
        "{%0,%1,%2,%3}, {%4,%5,%6,%7}, {%8,%9}, {%0,%1,%2,%3};"
        : "+f"(c[0]), "+f"(c[1]), "+f"(c[2]), "+f"(c[3])
        : "r"(a0), "r"(a1), "r"(a2), "r"(a3), "r"(b0), "r"(b1));
}

__device__ __forceinline__ void ldsm4(uint32_t* r, uint32_t addr) {
    asm volatile("ldmatrix.sync.aligned.m8n8.x4.shared.b16 {%0,%1,%2,%3}, [%4];"
                 : "=r"(r[0]), "=r"(r[1]), "=r"(r[2]), "=r"(r[3]) : "r"(addr));
}

__device__ __forceinline__ void mm_compute(uint32_t aBase, uint32_t bBase,
                                           float (&acc)[4][4][4]) {
#pragma unroll
    for (int ks = 0; ks < 2; ks++) {
        uint32_t a[4][4], b[2][4];
#pragma unroll
        for (int mi = 0; mi < 4; mi++) ldsm4(a[mi], aBase + mi * (16 * SMA * 2) + ks * 32);
#pragma unroll
        for (int p = 0; p < 2; p++) ldsm4(b[p], bBase + p * (16 * SMA * 2) + ks * 32);
#pragma unroll
        for (int mi = 0; mi < 4; mi++)
#pragma unroll
            for (int ni = 0; ni < 4; ni++) {
                int p = ni >> 1, s = (ni & 1) * 2;
                mma_bf16(acc[mi][ni], a[mi][0], a[mi][1], a[mi][2], a[mi][3],
                         b[p][s], b[p][s + 1]);
            }
    }
}

#define CPA16(dst, src) \
    asm volatile("cp.async.cg.shared.global [%0], [%1], 16;" :: "r"(dst), "l"(src))
#define CPA_COMMIT() asm volatile("cp.async.commit_group;" ::: "memory")
#define CPA_WAIT0()  asm volatile("cp.async.wait_group 0;" ::: "memory")

// ============ fat kernel A: xsplit ∥ wres ∥ rsplit ∥ zero (all input-only) ============
__global__ void __launch_bounds__(256) k_fatA(const float* __restrict__ x,
                                              const float* __restrict__ w,
                                              const float* __restrict__ U,
                                              const float* __restrict__ R0,
                                              const float* __restrict__ R1,
                                              const float* __restrict__ V) {
    int b = blockIdx.x;
    if (b < 8192) {
        // ---- xsplit ----
        size_t base = ((size_t)b * 256 + threadIdx.x) * 16;
        __nv_bfloat16 h16[16], m16[16];
#pragma unroll
        for (int j = 0; j < 4; j++) {
            float4 v = *(const float4*)(x + base + j * 4);
            float vv[4] = {v.x, v.y, v.z, v.w};
#pragma unroll
            for (int q = 0; q < 4; q++) {
                __nv_bfloat16 h = __float2bfloat16_rn(vv[q]);
                h16[j * 4 + q] = h;
                m16[j * 4 + q] = __float2bfloat16_rn(vv[q] - __bfloat162float(h));
            }
        }
        *(uint4*)&g_xh[base]     = *(uint4*)&h16[0];
        *(uint4*)&g_xh[base + 8] = *(uint4*)&h16[8];
        *(uint4*)&g_xm[base]     = *(uint4*)&m16[0];
        *(uint4*)&g_xm[base + 8] = *(uint4*)&m16[8];
    } else if (b < 9216) {
        // ---- wres ----
        int o = b - 8192;
        __shared__ float u[TR];
        if (threadIdx.x < TR) u[threadIdx.x] = U[o * TR + threadIdx.x];
        __syncthreads();
        for (int c = threadIdx.x; c < TC; c += 256) {
            float acc = w[(size_t)o * TC + c];
#pragma unroll
            for (int r = 0; r < TR; r++) acc = __fmaf_rn(-u[r], V[r * TC + c], acc);
            g_wres[(size_t)o * TC + c] = acc;
        }
    } else if (b < 10240) {
        // ---- rsplit + fp32 transpose ----
        int idx = b - 9216;
        int half = idx >> 9, n = idx & 511;
        const float* R = half ? R1 : R0;
        size_t ob = (size_t)half * TH * TH + (size_t)n * TH;
        for (int k = threadIdx.x; k < TH; k += 256) {
            float v = R[(size_t)k * TH + n];
            __nv_bfloat16 h = __float2bfloat16_rn(v);
            g_rh[ob + k] = h;
            g_rm[ob + k] = __float2bfloat16_rn(v - __bfloat162float(h));
            g_rt[ob + k] = v;
        }
    } else {
        if (threadIdx.x == 0) g_flagcnt = 0;
    }
}

// ------- 2) weight rotate (Kahan fp32) + static quant -> bf16 codes -------
__global__ void __launch_bounds__(256) k_wrotq(const float* __restrict__ R0,
                                               const float* __restrict__ R1,
                                               const float* __restrict__ ws0,
                                               const float* __restrict__ ws1) {
    int half = blockIdx.y;
    const float* R = half ? R1 : R0;
    const float* ws = half ? ws1 : ws0;
    int o0 = blockIdx.x * 4;
    __shared__ float wr[4][TH];
    for (int i = threadIdx.x; i < 4 * TH; i += 256)
        wr[i >> 9][i & 511] = g_wres[(size_t)(o0 + (i >> 9)) * TC + half * TH + (i & 511)];
    __syncthreads();
    int n = threadIdx.x;
    float s[4][2] = {}, c[4][2] = {};
    for (int k = 0; k < TH; k++) {
        float b0 = R[k * TH + n], b1 = R[k * TH + n + 256];
#pragma unroll
        for (int i = 0; i < 4; i++) {
            float a = wr[i][k];
            float p0 = __fmul_rn(a, b0);
            float y0 = __fadd_rn(p0, -c[i][0]);
            float t0 = __fadd_rn(s[i][0], y0);
            c[i][0] = __fadd_rn(__fadd_rn(t0, -s[i][0]), -y0);
            s[i][0] = t0;
            float p1 = __fmul_rn(a, b1);
            float y1 = __fadd_rn(p1, -c[i][1]);
            float t1 = __fadd_rn(s[i][1], y1);
            c[i][1] = __fadd_rn(__fadd_rn(t1, -s[i][1]), -y1);
            s[i][1] = t1;
        }
    }
#pragma unroll
    for (int i = 0; i < 4; i++) {
        float sw = ws[o0 + i];
        g_qwb[(size_t)(o0 + i) * TC + half * TH + n]       = __float2bfloat16_rn(qcode(s[i][0], sw));
        g_qwb[(size_t)(o0 + i) * TC + half * TH + n + 256] = __float2bfloat16_rn(qcode(s[i][1], sw));
    }
}

// ------- 3) x rotation: bf16 HMMA, 3 passes, double-buffered cp.async, 2 CTAs/SM -------
#define XBUFB (128 * SMA * 2)   // bytes per operand array (10240)

__global__ void __launch_bounds__(256, 2) k_xrot() {
    extern __shared__ __align__(16) char xsm[];
    const int half = blockIdx.z;
    const int n0 = blockIdx.x * 128, m0 = blockIdx.y * 128;
    const int tid = threadIdx.x, lane = tid & 31, wid = tid >> 5;
    const int wm = wid >> 2, wn = wid & 3;
    uint32_t sbase = (uint32_t)__cvta_generic_to_shared(xsm);

    float acc[4][4][4];
#pragma unroll
    for (int i = 0; i < 4; i++)
#pragma unroll
        for (int j = 0; j < 4; j++)
#pragma unroll
            for (int c = 0; c < 4; c++) acc[i][j][c] = 0.0f;

    const int g = lane >> 3, r = lane & 7;
    uint32_t aoff = (uint32_t)(((wm * 64 + (g & 1) * 8 + r) * SMA + (g >> 1) * 8) * 2);
    uint32_t boff = (uint32_t)(((wn * 32 + (g >> 1) * 8 + r) * SMA + (g & 1) * 8) * 2);

    const int srow = tid >> 1, skq = (tid & 1) * 16;
    const uint32_t stoff = (uint32_t)((srow * SMA + skq) * 2);
    const __nv_bfloat16* Axh = g_xh + (size_t)(m0 + srow) * TC + half * TH + skq;
    const __nv_bfloat16* Axm = g_xm + (size_t)(m0 + srow) * TC + half * TH + skq;
    const __nv_bfloat16* Brh = g_rh + (size_t)half * TH * TH + (size_t)(n0 + srow) * TH + skq;
    const __nv_bfloat16* Brm = g_rm + (size_t)half * TH * TH + (size_t)(n0 + srow) * TH + skq;

    auto issue = [&](int buf, int k0) {
        uint32_t b = sbase + (uint32_t)buf * (4 * XBUFB) + stoff;
        CPA16(b,                  Axh + k0);
        CPA16(b + 16,             Axh + k0 + 8);
        CPA16(b + XBUFB,          Axm + k0);
        CPA16(b + XBUFB + 16,     Axm + k0 + 8);
        CPA16(b + 2 * XBUFB,      Brh + k0);
        CPA16(b + 2 * XBUFB + 16, Brh + k0 + 8);
        CPA16(b + 3 * XBUFB,      Brm + k0);
        CPA16(b + 3 * XBUFB + 16, Brm + k0 + 8);
        CPA_COMMIT();
    };

    issue(0, 0);
    for (int it = 0; it < 16; it++) {
        CPA_WAIT0();
        __syncthreads();
        if (it < 15) issue((it + 1) & 1, (it + 1) * 32);
        uint32_t bb = sbase + (uint32_t)(it & 1) * (4 * XBUFB);
        mm_compute(bb + aoff, bb + 3 * XBUFB + boff, acc);              // h*m
        mm_compute(bb + XBUFB + aoff, bb + 2 * XBUFB + boff, acc);      // m*h
        mm_compute(bb + aoff, bb + 2 * XBUFB + boff, acc);              // h*h
        __syncthreads();
    }

    const int qrow = lane >> 2, qcol = (lane & 3) * 2;
#pragma unroll
    for (int mi = 0; mi < 4; mi++) {
        size_t row = m0 + wm * 64 + mi * 16 + qrow;
#pragma unroll
        for (int ni = 0; ni < 4; ni++) {
            int col = half * TH + n0 + wn * 32 + ni * 8 + qcol;
            *(float2*)&g_x[row * TC + col] = make_float2(acc[mi][ni][0], acc[mi][ni][1]);
            *(float2*)&g_x[(row + 8) * TC + col] = make_float2(acc[mi][ni][2], acc[mi][ni][3]);
        }
    }
}

// ------- 4) p = x @ V^T via bf16 3-pass MMA, 2 CTAs/SM -------
__global__ void __launch_bounds__(256, 2) k_p(const float* __restrict__ V) {
    __shared__ __align__(16) __nv_bfloat16 Ah[128 * SMA], Am[128 * SMA];
    __shared__ __align__(16) __nv_bfloat16 Bh[32 * SMA], Bm[32 * SMA];
    const int m0 = blockIdx.x * 128;
    const int tid = threadIdx.x, lane = tid & 31, wid = tid >> 5;

    float acc[4][4];
#pragma unroll
    for (int i = 0; i < 4; i++)
#pragma unroll
        for (int c = 0; c < 4; c++) acc[i][c] = 0.0f;

    const int g = lane >> 3, r = lane & 7;
    uint32_t smAh = (uint32_t)__cvta_generic_to_shared(Ah);
    uint32_t smAm = (uint32_t)__cvta_generic_to_shared(Am);
    uint32_t smBh = (uint32_t)__cvta_generic_to_shared(Bh);
    uint32_t smBm = (uint32_t)__cvta_generic_to_shared(Bm);
    uint32_t aoff = (uint32_t)(((wid * 16 + (g & 1) * 8 + r) * SMA + (g >> 1) * 8) * 2);
    uint32_t boff = (uint32_t)((((g >> 1) * 8 + r) * SMA + (g & 1) * 8) * 2);

    const int srow = tid >> 1, skq = (tid & 1) * 16;
    const __nv_bfloat16* Axh = g_xh + (size_t)(m0 + srow) * TC + skq;
    const __nv_bfloat16* Axm = g_xm + (size_t)(m0 + srow) * TC + skq;
    const int vr = tid >> 3, vkq = (tid & 7) * 4;
    const float* Vg = V + (size_t)vr * TC + vkq;

    uint4 a0 = *(const uint4*)Axh, a1 = *(const uint4*)(Axh + 8);
    uint4 a2 = *(const uint4*)Axm, a3 = *(const uint4*)(Axm + 8);
    float4 bv = *(const float4*)Vg;

    for (int it = 0; it < 32; it++) {
        *(uint4*)&Ah[srow * SMA + skq]     = a0;
        *(uint4*)&Ah[srow * SMA + skq + 8] = a1;
        *(uint4*)&Am[srow * SMA + skq]     = a2;
        *(uint4*)&Am[srow * SMA + skq + 8] = a3;
        {
            float vv[4] = {bv.x, bv.y, bv.z, bv.w};
            __nv_bfloat16 h4[4], m4[4];
#pragma unroll
            for (int q = 0; q < 4; q++) {
                __nv_bfloat16 h = __float2bfloat16_rn(vv[q]);
                h4[q] = h;
                m4[q] = __float2bfloat16_rn(vv[q] - __bfloat162float(h));
            }
            *(uint2*)&Bh[vr * SMA + vkq] = *(uint2*)h4;
            *(uint2*)&Bm[vr * SMA + vkq] = *(uint2*)m4;
        }
        __syncthreads();
        if (it < 31) {
            int k0 = (it + 1) * 32;
            a0 = *(const uint4*)(Axh + k0);  a1 = *(const uint4*)(Axh + k0 + 8);
            a2 = *(const uint4*)(Axm + k0);  a3 = *(const uint4*)(Axm + k0 + 8);
            bv = *(const float4*)(Vg + k0);
        }
#pragma unroll 1
        for (int pass = 0; pass < 3; pass++) {
            uint32_t aB = (pass == 1) ? smAm + aoff : smAh + aoff;
            uint32_t bB = (pass == 0) ? smBm + boff : smBh + boff;
#pragma unroll
            for (int ks = 0; ks < 2; ks++) {
                uint32_t a[4], b[2][4];
                ldsm4(a, aB + ks * 32);
                ldsm4(b[0], bB + ks * 32);
                ldsm4(b[1], bB + 16 * SMA * 2 + ks * 32);
#pragma unroll
                for (int ni = 0; ni < 4; ni++) {
                    int p = ni >> 1, s = (ni & 1) * 2;
                    mma_bf16(acc[ni], a[0], a[1], a[2], a[3], b[p][s], b[p][s + 1]);
                }
            }
        }
        __syncthreads();
    }

    const int qrow = lane >> 2, qcol = (lane & 3) * 2;
#pragma unroll
    for (int ni = 0; ni < 4; ni++) {
        size_t row = m0 + wid * 16 + qrow;
        int col = ni * 8 + qcol;
        *(float2*)&g_p[row * TR + col]       = make_float2(acc[ni][0], acc[ni][1]);
        *(float2*)&g_p[(row + 8) * TR + col] = make_float2(acc[ni][2], acc[ni][3]);
    }
}

// -------- 5b) dynamic quant: warp-per-half-token, shfl-only reduction --------
__global__ void __launch_bounds__(256) k_quant() {
    int wid = threadIdx.x >> 5, lane = threadIdx.x & 31;
    size_t t = (size_t)blockIdx.x * 4 + (wid >> 1);
    int half = wid & 1;
    const float* xr = g_x + t * TC + half * TH;

    float4 v[4];
    float m = 0.0f;
    int mi = 0;
#pragma unroll
    for (int j = 0; j < 4; j++) {
        int base = lane * 4 + j * 128;
        v[j] = *(const float4*)(xr + base);
        float a[4] = {fabsf(v[j].x), fabsf(v[j].y), fabsf(v[j].z), fabsf(v[j].w)};
#pragma unroll
        for (int q = 0; q < 4; q++)
            if (a[q] > m || (a[q] == m && base + q < mi)) { m = a[q]; mi = base + q; }
    }
#pragma unroll
    for (int o = 16; o; o >>= 1) {
        float om = __shfl_xor_sync(0xffffffffu, m, o);
        int   oi = __shfl_xor_sync(0xffffffffu, mi, o);
        if (om > m || (om == m && oi < mi)) { m = om; mi = oi; }
    }
    float s = fmaxf(__fdiv_rn(m, 7.0f), 1e-8f);
    if (lane == 0) {
        if (half) g_s1[t] = s; else g_s0[t] = s;
        g_aidx[t * 2 + half] = mi;
    }

    __nv_bfloat16* qr = g_qx + t * TC + half * TH;
#pragma unroll
    for (int j = 0; j < 4; j++) {
        int base = lane * 4 + j * 128;
        float vv[4] = {v[j].x, v[j].y, v[j].z, v[j].w};
        __nv_bfloat16 cd[4];
#pragma unroll
        for (int q = 0; q < 4; q++) {
            float u = __fdiv_rn(vv[q], s);
            float rr = rintf(u);
            cd[q] = __float2bfloat16_rn(fminf(fmaxf(rr, -8.0f), 7.0f));
            if (0.5f - fabsf(u - rr) < TAU) {
                int idx = atomicAdd(&g_flagcnt, 1);
                if (idx < FCAP) g_flags[idx] = ((int)t << 10) | (half * TH + base + q);
            }
        }
        *(uint2*)(qr + base) = *(uint2*)cd;
    }
}

// -------- 5c) fix-up: exact serial fp32 chain, CONTIGUOUS loads via R^T --------
__global__ void __launch_bounds__(256) k_fix(const float* __restrict__ x) {
    int cnt = g_flagcnt;
    if (cnt > FCAP) cnt = FCAP;
    for (int i = blockIdx.x * blockDim.x + threadIdx.x; i < cnt;
         i += gridDim.x * blockDim.x) {
        int e = g_flags[i];
        int t = e >> 10, c = e & 1023;
        int h = c >> 9, cc = c & 511;
        const float4* xr = (const float4*)(x + (size_t)t * TC + h * TH);
        const float4* rc = (const float4*)(g_rt + (size_t)h * TH * TH + (size_t)cc * TH);
        int ac = g_aidx[t * 2 + h];
        const float4* ra = (const float4*)(g_rt + (size_t)h * TH * TH + (size_t)ac * TH);
        float v = 0.0f, va = 0.0f;
#pragma unroll 4
        for (int k4 = 0; k4 < TH / 4; k4++) {
            float4 xv = xr[k4];
            float4 c4 = rc[k4];
            float4 a4 = ra[k4];
            v  = __fmaf_rn(xv.x, c4.x, v);  va = __fmaf_rn(xv.x, a4.x, va);
            v  = __fmaf_rn(xv.y, c4.y, v);  va = __fmaf_rn(xv.y, a4.y, va);
            v  = __fmaf_rn(xv.z, c4.z, v);  va = __fmaf_rn(xv.z, a4.z, va);
            v  = __fmaf_rn(xv.w, c4.w, v);  va = __fmaf_rn(xv.w, a4.w, va);
        }
        float s = fmaxf(__fdiv_rn(fabsf(va), 7.0f), 1e-8f);
        g_qx[(size_t)t * TC + c] = __float2bfloat16_rn(qcode(v, s));
    }
}

// ---- 6) main GEMM: bf16 HMMA + fused skip/affine, double-buffered cp.async ----
#define MBUF (128 * SMA * 2)   // 10240 bytes per As or Bs

__global__ void __launch_bounds__(256, 2) k_main(const float* __restrict__ U,
                                                 const float* __restrict__ bias,
                                                 const float* __restrict__ ws0,
                                                 const float* __restrict__ ws1,
                                                 const float* __restrict__ gamma,
                                                 const float* __restrict__ beta,
                                                 float* __restrict__ out) {
    extern __shared__ __align__(16) char msm[];
    __nv_bfloat16* As0 = (__nv_bfloat16*)msm;
    __nv_bfloat16* Bs0 = (__nv_bfloat16*)(msm + MBUF);
    const int tid = threadIdx.x;
    const int lane = tid & 31, wid = tid >> 5;
    const int wm = wid >> 2, wn = wid & 3;
    const int n0 = blockIdx.x * 128, m0 = blockIdx.y * 128;
    uint32_t sbase = (uint32_t)__cvta_generic_to_shared(msm);

    float acc[4][4][4];
#pragma unroll
    for (int i = 0; i < 4; i++)
#pragma unroll
        for (int j = 0; j < 4; j++)
#pragma unroll
            for (int c = 0; c < 4; c++) acc[i][j][c] = 0.0f;

    const int g = lane >> 3, r = lane & 7;
    uint32_t aoff = (uint32_t)(((wm * 64 + (g & 1) * 8 + r) * SMA + (g >> 1) * 8) * 2);
    uint32_t boff = (uint32_t)(((wn * 32 + (g >> 1) * 8 + r) * SMA + (g & 1) * 8) * 2);

    const int lrow = tid >> 2, lq = (tid & 3) * 8;
    const uint32_t st0 = (uint32_t)((lrow * SMA + lq) * 2);
    const uint32_t st1 = (uint32_t)(((lrow + 64) * SMA + lq) * 2);
    const __nv_bfloat16* Ag = g_qx + (size_t)m0 * TC + lq;
    const __nv_bfloat16* Bg = g_qwb + (size_t)n0 * TC + lq;

    auto issue = [&](int buf, int k0) {
        uint32_t b = sbase + (uint32_t)buf * (2 * MBUF);
        CPA16(b + st0,        Ag + (size_t)lrow * TC + k0);
        CPA16(b + st1,        Ag + (size_t)(lrow + 64) * TC + k0);
        CPA16(b + MBUF + st0, Bg + (size_t)lrow * TC + k0);
        CPA16(b + MBUF + st1, Bg + (size_t)(lrow + 64) * TC + k0);
        CPA_COMMIT();
    };

    const int qrow = lane >> 2, qcol = (lane & 3) * 2;

    issue(0, 0);
    for (int it = 0; it < 32; it++) {
        CPA_WAIT0();
        __syncthreads();
        if (it < 31) issue((it + 1) & 1, (it + 1) * 32);
        uint32_t bb = sbase + (uint32_t)(it & 1) * (2 * MBUF);
        mm_compute(bb + aoff, bb + MBUF + boff, acc);
        if (it == 15) {
            float rr[4][2], rc[4][2];
#pragma unroll
            for (int mi = 0; mi < 4; mi++) {
                int rw = m0 + wm * 64 + mi * 16 + qrow;
                rr[mi][0] = __fdiv_rn(g_s0[rw], g_s1[rw]);
                rr[mi][1] = __fdiv_rn(g_s0[rw + 8], g_s1[rw + 8]);
            }
#pragma unroll
            for (int ni = 0; ni < 4; ni++) {
                int cl = n0 + wn * 32 + ni * 8 + qcol;
                rc[ni][0] = __fdiv_rn(ws0[cl], ws1[cl]);
                rc[ni][1] = __fdiv_rn(ws0[cl + 1], ws1[cl + 1]);
            }
#pragma unroll
            for (int mi = 0; mi < 4; mi++)
#pragma unroll
                for (int ni = 0; ni < 4; ni++) {
                    acc[mi][ni][0] *= rr[mi][0] * rc[ni][0];
                    acc[mi][ni][1] *= rr[mi][0] * rc[ni][1];
                    acc[mi][ni][2] *= rr[mi][1] * rc[ni][0];
                    acc[mi][ni][3] *= rr[mi][1] * rc[ni][1];
                }
        }
    }

    {
        float sr[4][2], sc[4][2];
#pragma unroll
        for (int mi = 0; mi < 4; mi++) {
            int rw = m0 + wm * 64 + mi * 16 + qrow;
            sr[mi][0] = g_s1[rw];
            sr[mi][1] = g_s1[rw + 8];
        }
#pragma unroll
        for (int ni = 0; ni < 4; ni++) {
            int cl = n0 + wn * 32 + ni * 8 + qcol;
            sc[ni][0] = ws1[cl];
            sc[ni][1] = ws1[cl + 1];
        }
#pragma unroll
        for (int mi = 0; mi < 4; mi++)
#pragma unroll
            for (int ni = 0; ni < 4; ni++) {
                acc[mi][ni][0] *= sr[mi][0] * sc[ni][0];
                acc[mi][ni][1] *= sr[mi][0] * sc[ni][1];
                acc[mi][ni][2] *= sr[mi][1] * sc[ni][0];
                acc[mi][ni][3] *= sr[mi][1] * sc[ni][1];
            }
    }

#pragma unroll 1
    for (int pass = 0; pass < 3; pass++) {
        __syncthreads();
#pragma unroll
        for (int l = 0; l < 16; l++) {
            int idx = tid + l * 256, row = idx >> 5, c = idx & 31;
            if (pass != 1) {
                float v = g_p[(size_t)(m0 + row) * TR + c];
                __nv_bfloat16 h = __float2bfloat16_rn(v);
                As0[row * SMA + c] =
                    (pass == 2) ? __float2bfloat16_rn(v - __bfloat162float(h)) : h;
            }
            {
                float v = U[(size_t)(n0 + row) * TR + c];
                __nv_bfloat16 h = __float2bfloat16_rn(v);
                Bs0[row * SMA + c] =
                    (pass == 1) ? __float2bfloat16_rn(v - __bfloat162float(h)) : h;
            }
        }
        __syncthreads();
        mm_compute(sbase + aoff, sbase + MBUF + boff, acc);
    }

    float bi[4][2], ga[4][2], be[4][2];
#pragma unroll
    for (int ni = 0; ni < 4; ni++) {
        int cl = n0 + wn * 32 + ni * 8 + qcol;
        bi[ni][0] = bias[cl];  bi[ni][1] = bias[cl + 1];
        ga[ni][0] = gamma[cl]; ga[ni][1] = gamma[cl + 1];
        be[ni][0] = beta[cl];  be[ni][1] = beta[cl + 1];
    }
#pragma unroll
    for (int mi = 0; mi < 4; mi++) {
        size_t r0 = m0 + wm * 64 + mi * 16 + qrow;
#pragma unroll
        for (int ni = 0; ni < 4; ni++) {
            int cl = n0 + wn * 32 + ni * 8 + qcol;
            float2 o0, o1;
            o0.x = __fmaf_rn(acc[mi][ni][0] + bi[ni][0], ga[ni][0], be[ni][0]);
            o0.y = __fmaf_rn(acc[mi][ni][1] + bi[ni][1], ga[ni][1], be[ni][1]);
            o1.x = __fmaf_rn(acc[mi][ni][2] + bi[ni][0], ga[ni][0], be[ni][0]);
            o1.y = __fmaf_rn(acc[mi][ni][3] + bi[ni][1], ga[ni][1], be[ni][1]);
            *(float2*)&out[r0 * TO + cl] = o0;
            *(float2*)&out[(r0 + 8) * TO + cl] = o1;
        }
    }
}

extern "C" void kernel_launch(void* const* d_in, const int* in_sizes, int n_in,
                              void* d_out, int out_size) {
    const float* x     = (const float*)d_in[0];
    const float* w     = (const float*)d_in[1];
    const float* bias  = (const float*)d_in[2];
    const float* U     = (const float*)d_in[3];
    const float* V     = (const float*)d_in[4];
    const float* R0    = (const float*)d_in[5];
    const float* R1    = (const float*)d_in[6];
    const float* ws0   = (const float*)d_in[7];
    const float* ws1   = (const float*)d_in[8];
    const float* gamma = (const float*)d_in[9];
    const float* beta  = (const float*)d_in[10];
    float* out = (float*)d_out;

    cudaFuncSetAttribute(k_xrot, cudaFuncAttributeMaxDynamicSharedMemorySize,
                         8 * XBUFB);

    k_fatA<<<10241, 256>>>(x, w, U, R0, R1, V);
    k_wrotq<<<dim3(256, 2), 256>>>(R0, R1, ws0, ws1);
    k_xrot<<<dim3(4, 256, 2), 256, 8 * XBUFB>>>();
    k_p<<<256, 256>>>(V);
    k_quant<<<MT / 4, 256>>>();
    k_fix<<<512, 256>>>(x);
    k_main<<<dim3(8, 256), 256, 4 * MBUF>>>(U, bias, ws0, ws1, gamma, beta, out);
}